// round 2
// baseline (speedup 1.0000x reference)
#include <cuda_runtime.h>

// MSELoss: out = mean((yhat - y)^2) over 16384 x 4096 fp32.
// Single persistent-wave streaming reduction:
//  - 592 blocks = 148 SMs x 4 resident blocks (one wave, no wave transitions)
//  - 2x-unrolled float4 loads (4 LDG.128 in flight per iter) for deep MLP
//  - block reduce -> atomicAdd into __device__ scratch
//  - threadfence last-block-done pattern writes d_out and resets scratch
//    (deterministic per launch, no memset node needed)

#define BLOCK 256
#define GRID  592   // 148 SMs * 4 blocks (regs low enough for full residency)

__device__ float    g_sum   = 0.0f;
__device__ unsigned g_count = 0u;

__global__ void __launch_bounds__(BLOCK, 4)
mse_kernel(const float4* __restrict__ yhat,
           const float4* __restrict__ y,
           float* __restrict__ out,
           int n4, float inv_n) {
    float acc = 0.0f;
    const int stride = GRID * BLOCK;
    int i = blockIdx.x * BLOCK + threadIdx.x;

    // main unrolled-by-2 stream: 4 independent 128b loads per iteration
    for (; i + stride < n4; i += 2 * stride) {
        float4 a0 = __ldg(&yhat[i]);
        float4 b0 = __ldg(&y[i]);
        float4 a1 = __ldg(&yhat[i + stride]);
        float4 b1 = __ldg(&y[i + stride]);
        float d;
        d = a0.x - b0.x; acc = fmaf(d, d, acc);
        d = a0.y - b0.y; acc = fmaf(d, d, acc);
        d = a0.z - b0.z; acc = fmaf(d, d, acc);
        d = a0.w - b0.w; acc = fmaf(d, d, acc);
        d = a1.x - b1.x; acc = fmaf(d, d, acc);
        d = a1.y - b1.y; acc = fmaf(d, d, acc);
        d = a1.z - b1.z; acc = fmaf(d, d, acc);
        d = a1.w - b1.w; acc = fmaf(d, d, acc);
    }
    // tail
    if (i < n4) {
        float4 a = __ldg(&yhat[i]);
        float4 b = __ldg(&y[i]);
        float d;
        d = a.x - b.x; acc = fmaf(d, d, acc);
        d = a.y - b.y; acc = fmaf(d, d, acc);
        d = a.z - b.z; acc = fmaf(d, d, acc);
        d = a.w - b.w; acc = fmaf(d, d, acc);
    }

    // warp reduce
    #pragma unroll
    for (int off = 16; off > 0; off >>= 1)
        acc += __shfl_xor_sync(0xFFFFFFFFu, acc, off);

    __shared__ float warp_sums[BLOCK / 32];
    int lane = threadIdx.x & 31;
    int wid  = threadIdx.x >> 5;
    if (lane == 0) warp_sums[wid] = acc;
    __syncthreads();

    if (threadIdx.x == 0) {
        float bsum = 0.0f;
        #pragma unroll
        for (int w = 0; w < BLOCK / 32; w++) bsum += warp_sums[w];

        // last-block-done: prior = sum of all other blocks' contributions
        float prior = atomicAdd(&g_sum, bsum);
        __threadfence();
        unsigned t = atomicAdd(&g_count, 1u);
        if (t == GRID - 1) {
            out[0] = (prior + bsum) * inv_n;
            g_sum   = 0.0f;   // reset for next graph replay
            g_count = 0u;
        }
    }
}

extern "C" void kernel_launch(void* const* d_in, const int* in_sizes, int n_in,
                              void* d_out, int out_size) {
    const float4* yhat = (const float4*)d_in[0];
    const float4* y    = (const float4*)d_in[1];
    float* out = (float*)d_out;

    long long n = (long long)in_sizes[0];   // 67108864
    int n4 = (int)(n / 4);                  // 16777216
    float inv_n = 1.0f / (float)n;

    mse_kernel<<<GRID, BLOCK>>>(yhat, y, out, n4, inv_n);
}